// round 7
// baseline (speedup 1.0000x reference)
#include <cuda_runtime.h>
#include <stdint.h>

#define Nn 2048
#define Ff 32
#define Ee 16
#define Kk 32

// Scratch (device globals — no allocation allowed)
__device__ float g_u[Nn * Ff];    // node_part + b_ne
__device__ float g_pre[Nn * Ff];  // (1+eps) * relu(nodes@W_n + b_n)

// Kernel A: per-node precompute. 65536 threads, one per (j,f).
__global__ void prep_kernel(const float* __restrict__ nodes,
                            const float* __restrict__ W_ne,
                            const float* __restrict__ b_ne,
                            const float* __restrict__ W_n,
                            const float* __restrict__ b_n,
                            const float* __restrict__ eps) {
    int t = blockIdx.x * blockDim.x + threadIdx.x;  // 0..N*F-1
    int j = t >> 5;
    int f = t & 31;
    const float* nrow = nodes + j * Ff;
    float s1 = 0.f, s2 = 0.f;
#pragma unroll
    for (int c = 0; c < Ff; c++) {
        float nv = nrow[c];
        s1 = fmaf(nv, W_ne[c * Ff + f], s1);  // node part of W_ne (rows [0,F))
        s2 = fmaf(nv, W_n[c * Ff + f], s2);
    }
    g_u[t] = s1 + b_ne[f];
    g_pre[t] = (1.0f + eps[0]) * fmaxf(s2 + b_n[f], 0.f);
}

// Warp-specialized fused kernel: one block per row i.
//   Warps 0-5 : stream the 128 KB edges[i] row -> out_edges (pure bandwidth,
//               starts immediately, runs the whole block lifetime).
//   Warps 6-7 : adj scan + adj->out copy + ballot compaction, then the sparse
//               edge matmul + relu + masked sum (2-way unrolled for MLP),
//               then block epilogue ((1+eps)*node_term + msg, 32x32 FC, relu).
//   The latency-bound sparse work hides entirely behind the copy warps, so
//   the SM streams DRAM from first cycle to last. No __syncthreads; the two
//   sparse warps sync via named barrier 1.
__global__ __launch_bounds__(256) void fused_kernel(
    const float* __restrict__ adj,
    const float* __restrict__ edges,
    const float* __restrict__ W_ne,
    const float* __restrict__ W_net,
    const float* __restrict__ b_net,
    float* __restrict__ out_adj,
    float* __restrict__ out_y,
    float* __restrict__ out_edges) {
    int i = blockIdx.x;
    int t = threadIdx.x;
    int lane = t & 31;
    int w = t >> 5;  // warp 0..7

    __shared__ uint16_t sj[2][Nn / 2];  // compacted neighbor indices per warp
    __shared__ float sa[2][Nn / 2];     // corresponding adj values
    __shared__ float smsg[2][32];

    const float* erow = edges + (size_t)i * Nn * Ee;
    const float4* erow4 = reinterpret_cast<const float4*>(erow);

    if (w < 6) {
        // ================= COPY WARPS (0-5): 8192 float4, 192 threads =======
        float4* oe4 = reinterpret_cast<float4*>(out_edges + (size_t)i * Nn * Ee);
        int idx = t;  // t in [0,192)
        // 40 guaranteed iterations in batches of 4 (high MLP).
#pragma unroll 2
        for (int r = 0; r < 10; r++) {
            float4 a0 = erow4[idx + 0 * 192];
            float4 a1 = erow4[idx + 1 * 192];
            float4 a2 = erow4[idx + 2 * 192];
            float4 a3 = erow4[idx + 3 * 192];
            oe4[idx + 0 * 192] = a0;
            oe4[idx + 1 * 192] = a1;
            oe4[idx + 2 * 192] = a2;
            oe4[idx + 3 * 192] = a3;
            idx += 4 * 192;
        }
        // Remainder (512 float4).
        for (; idx < Nn * Ee / 4; idx += 192) oe4[idx] = erow4[idx];
    } else {
        // ================= SPARSE WARPS (6-7) ===============================
        int sw = w - 6;  // 0 or 1
        const float* adjrow = adj + (size_t)i * Nn;
        float* oadj = out_adj + (size_t)i * Nn;

        // --- adj scan + copy + compaction: warp sw owns 32 chunks of 64 ---
        int cnt = 0;
#pragma unroll 4
        for (int c = 0; c < 32; c++) {
            int jb = c * 64 + sw * 32;
            float a = adjrow[jb + lane];
            oadj[jb + lane] = a;  // fused adj pass-through copy
            unsigned mask = __ballot_sync(0xffffffffu, a != 0.f);
            int pos = cnt + __popc(mask & ((1u << lane) - 1u));
            if (a != 0.f) {
                sj[sw][pos] = (uint16_t)(jb + lane);
                sa[sw][pos] = a;
            }
            cnt += __popc(mask);
        }
        __syncwarp();

        // --- sparse message: 2-way unrolled for MLP ---
        float we[Ee];
#pragma unroll
        for (int e = 0; e < Ee; e++) we[e] = W_ne[(Ff + e) * Ff + lane];

        float msg = 0.f;
        int idx = 0;
        for (; idx + 2 <= cnt; idx += 2) {
            int j0 = sj[sw][idx];
            int j1 = sj[sw][idx + 1];
            float a0 = sa[sw][idx];
            float a1 = sa[sw][idx + 1];
            const float4* p0 = erow4 + (size_t)j0 * 4;
            const float4* p1 = erow4 + (size_t)j1 * 4;
            float4 x0 = p0[0], x1 = p0[1], x2 = p0[2], x3 = p0[3];
            float4 y0 = p1[0], y1 = p1[1], y2 = p1[2], y3 = p1[3];
            float u0 = g_u[j0 * Ff + lane];
            float u1 = g_u[j1 * Ff + lane];

            float s0 = x0.x * we[0];
            s0 = fmaf(x0.y, we[1], s0);
            s0 = fmaf(x0.z, we[2], s0);
            s0 = fmaf(x0.w, we[3], s0);
            s0 = fmaf(x1.x, we[4], s0);
            s0 = fmaf(x1.y, we[5], s0);
            s0 = fmaf(x1.z, we[6], s0);
            s0 = fmaf(x1.w, we[7], s0);
            s0 = fmaf(x2.x, we[8], s0);
            s0 = fmaf(x2.y, we[9], s0);
            s0 = fmaf(x2.z, we[10], s0);
            s0 = fmaf(x2.w, we[11], s0);
            s0 = fmaf(x3.x, we[12], s0);
            s0 = fmaf(x3.y, we[13], s0);
            s0 = fmaf(x3.z, we[14], s0);
            s0 = fmaf(x3.w, we[15], s0);

            float s1 = y0.x * we[0];
            s1 = fmaf(y0.y, we[1], s1);
            s1 = fmaf(y0.z, we[2], s1);
            s1 = fmaf(y0.w, we[3], s1);
            s1 = fmaf(y1.x, we[4], s1);
            s1 = fmaf(y1.y, we[5], s1);
            s1 = fmaf(y1.z, we[6], s1);
            s1 = fmaf(y1.w, we[7], s1);
            s1 = fmaf(y2.x, we[8], s1);
            s1 = fmaf(y2.y, we[9], s1);
            s1 = fmaf(y2.z, we[10], s1);
            s1 = fmaf(y2.w, we[11], s1);
            s1 = fmaf(y3.x, we[12], s1);
            s1 = fmaf(y3.y, we[13], s1);
            s1 = fmaf(y3.z, we[14], s1);
            s1 = fmaf(y3.w, we[15], s1);

            msg = fmaf(a0, fmaxf(s0 + u0, 0.f), msg);
            msg = fmaf(a1, fmaxf(s1 + u1, 0.f), msg);
        }
        if (idx < cnt) {
            int j0 = sj[sw][idx];
            float a0 = sa[sw][idx];
            const float4* p0 = erow4 + (size_t)j0 * 4;
            float4 x0 = p0[0], x1 = p0[1], x2 = p0[2], x3 = p0[3];
            float u0 = g_u[j0 * Ff + lane];
            float s0 = x0.x * we[0];
            s0 = fmaf(x0.y, we[1], s0);
            s0 = fmaf(x0.z, we[2], s0);
            s0 = fmaf(x0.w, we[3], s0);
            s0 = fmaf(x1.x, we[4], s0);
            s0 = fmaf(x1.y, we[5], s0);
            s0 = fmaf(x1.z, we[6], s0);
            s0 = fmaf(x1.w, we[7], s0);
            s0 = fmaf(x2.x, we[8], s0);
            s0 = fmaf(x2.y, we[9], s0);
            s0 = fmaf(x2.z, we[10], s0);
            s0 = fmaf(x2.w, we[11], s0);
            s0 = fmaf(x3.x, we[12], s0);
            s0 = fmaf(x3.y, we[13], s0);
            s0 = fmaf(x3.z, we[14], s0);
            s0 = fmaf(x3.w, we[15], s0);
            msg = fmaf(a0, fmaxf(s0 + u0, 0.f), msg);
        }

        smsg[sw][lane] = msg;
        // Named barrier between the two sparse warps only (threads 192-255).
        asm volatile("bar.sync 1, 64;" ::: "memory");

        if (sw == 0) {
            float m = smsg[0][lane] + smsg[1][lane];
            float p = g_pre[i * Ff + lane] + m;  // (1+eps)*node_term + msg
            float acc = b_net[lane];
#pragma unroll
            for (int f = 0; f < Ff; f++)
                acc = fmaf(__shfl_sync(0xffffffffu, p, f),
                           W_net[f * Kk + lane], acc);
            out_y[(size_t)i * Kk + lane] = fmaxf(acc, 0.f);
        }
    }
}

extern "C" void kernel_launch(void* const* d_in, const int* in_sizes, int n_in,
                              void* d_out, int out_size) {
    const float* adj = (const float*)d_in[0];
    const float* nodes = (const float*)d_in[1];
    const float* edges = (const float*)d_in[2];
    const float* W_ne = (const float*)d_in[3];
    const float* b_ne = (const float*)d_in[4];
    const float* W_n = (const float*)d_in[5];
    const float* b_n = (const float*)d_in[6];
    const float* W_net = (const float*)d_in[7];
    const float* b_net = (const float*)d_in[8];
    const float* eps = (const float*)d_in[9];

    float* out = (float*)d_out;
    float* out_adj = out;                                       // [N,N]
    float* out_y = out + (size_t)Nn * Nn;                       // [N,K]
    float* out_edges = out + (size_t)Nn * Nn + (size_t)Nn * Kk; // [N,N,E]

    prep_kernel<<<(Nn * Ff) / 256, 256>>>(nodes, W_ne, b_ne, W_n, b_n, eps);
    fused_kernel<<<Nn, 256>>>(adj, edges, W_ne, W_net, b_net, out_adj, out_y,
                              out_edges);
}

// round 9
// speedup vs baseline: 1.3261x; 1.3261x over previous
#include <cuda_runtime.h>
#include <stdint.h>

#define Nn 2048
#define Ff 32
#define Ee 16
#define Kk 32

#define NT 512        // threads per block (16 warps)
#define NV (Nn * Ee / 4)  // 8192 float4 per edges row

// smem layout (dynamic): tile | sj | sa | smsg
#define SM_TILE_B (NV * 16)                  // 131072
#define SM_SJ_B (16 * 128 * 2)               // 4096
#define SM_SA_B (16 * 128 * 4)               // 8192
#define SM_MSG_B (16 * 32 * 4)               // 2048
#define SM_TOTAL (SM_TILE_B + SM_SJ_B + SM_SA_B + SM_MSG_B)  // 145408

// Scratch (device globals — no allocation allowed)
__device__ float g_u[Nn * Ff];    // node_part + b_ne
__device__ float g_pre[Nn * Ff];  // (1+eps) * relu(nodes@W_n + b_n)

// Kernel A: per-node precompute. 65536 threads, one per (j,f).
__global__ void prep_kernel(const float* __restrict__ nodes,
                            const float* __restrict__ W_ne,
                            const float* __restrict__ b_ne,
                            const float* __restrict__ W_n,
                            const float* __restrict__ b_n,
                            const float* __restrict__ eps) {
    int t = blockIdx.x * blockDim.x + threadIdx.x;  // 0..N*F-1
    int j = t >> 5;
    int f = t & 31;
    const float* nrow = nodes + j * Ff;
    float s1 = 0.f, s2 = 0.f;
#pragma unroll
    for (int c = 0; c < Ff; c++) {
        float nv = nrow[c];
        s1 = fmaf(nv, W_ne[c * Ff + f], s1);
        s2 = fmaf(nv, W_n[c * Ff + f], s2);
    }
    g_u[t] = s1 + b_ne[f];
    g_pre[t] = (1.0f + eps[0]) * fmaxf(s2 + b_n[f], 0.f);
}

// One block per row i, 512 threads (16 warps).
//  1. adj scan (coalesced) + adj->out copy + per-warp ballot compaction.
//  2. stream edges[i] row gmem->out AND stage it into a 128 KB smem tile.
//  3. sparse msg: edge vectors from SMEM (29-cyc broadcast LDS, no DRAM/L2),
//     g_u from the L2-resident 256 KB table; 16 warps x ~6 nnz, 4-way MLP.
//  4. block reduce + 32x32 FC + relu.
__global__ __launch_bounds__(NT) void fused_kernel(
    const float* __restrict__ adj,
    const float* __restrict__ edges,
    const float* __restrict__ W_ne,
    const float* __restrict__ W_net,
    const float* __restrict__ b_net,
    float* __restrict__ out_adj,
    float* __restrict__ out_y,
    float* __restrict__ out_edges) {
    extern __shared__ char smraw[];
    float4* tile = reinterpret_cast<float4*>(smraw);
    uint16_t* sjb = reinterpret_cast<uint16_t*>(smraw + SM_TILE_B);
    float* sab = reinterpret_cast<float*>(smraw + SM_TILE_B + SM_SJ_B);
    float* smsg =
        reinterpret_cast<float*>(smraw + SM_TILE_B + SM_SJ_B + SM_SA_B);

    int i = blockIdx.x;
    int t = threadIdx.x;
    int lane = t & 31;
    int w = t >> 5;  // 0..15

    const float* adjrow = adj + (size_t)i * Nn;
    float* oadj = out_adj + (size_t)i * Nn;
    const float4* erow4 =
        reinterpret_cast<const float4*>(edges + (size_t)i * Nn * Ee);
    float4* oe4 = reinterpret_cast<float4*>(out_edges + (size_t)i * Nn * Ee);

    // ---- Phase 1: adj scan + copy + compaction (warp w owns 4 chunks) ----
    // Max 128 scanned positions per warp -> sj/sa[128] can never overflow.
    uint16_t* sj = sjb + w * 128;
    float* sa = sab + w * 128;
    int cnt = 0;
#pragma unroll
    for (int c = 0; c < 4; c++) {
        int jb = w * 32 + c * NT;
        float a = adjrow[jb + lane];
        oadj[jb + lane] = a;  // fused adj pass-through copy
        unsigned mask = __ballot_sync(0xffffffffu, a != 0.f);
        int pos = cnt + __popc(mask & ((1u << lane) - 1u));
        if (a != 0.f) {
            sj[pos] = (uint16_t)(jb + lane);
            sa[pos] = a;
        }
        cnt += __popc(mask);
    }

    // ---- Phase 2: stream copy + smem staging (16 float4 per thread) ----
#pragma unroll
    for (int r = 0; r < NV / NT; r++) {
        int k = t + r * NT;
        float4 v = erow4[k];
        oe4[k] = v;
        tile[k] = v;
    }
    __syncthreads();

    // ---- Phase 3: sparse message from the smem tile, 4-way unrolled ----
    float we[Ee];
#pragma unroll
    for (int e = 0; e < Ee; e++) we[e] = W_ne[(Ff + e) * Ff + lane];

    float msg = 0.f;
    int idx = 0;
    for (; idx + 4 <= cnt; idx += 4) {
        int j0 = sj[idx], j1 = sj[idx + 1], j2 = sj[idx + 2], j3 = sj[idx + 3];
        float a0 = sa[idx], a1 = sa[idx + 1], a2 = sa[idx + 2],
              a3 = sa[idx + 3];
        float u0 = g_u[j0 * Ff + lane];
        float u1 = g_u[j1 * Ff + lane];
        float u2 = g_u[j2 * Ff + lane];
        float u3 = g_u[j3 * Ff + lane];
        const float4 *p0 = tile + j0 * 4, *p1 = tile + j1 * 4,
                     *p2 = tile + j2 * 4, *p3 = tile + j3 * 4;
        float s0 = 0.f, s1 = 0.f, s2 = 0.f, s3 = 0.f;
#pragma unroll
        for (int q = 0; q < 4; q++) {
            float4 x = p0[q], y = p1[q], z = p2[q], v = p3[q];
            s0 = fmaf(x.x, we[4 * q + 0], s0);
            s0 = fmaf(x.y, we[4 * q + 1], s0);
            s0 = fmaf(x.z, we[4 * q + 2], s0);
            s0 = fmaf(x.w, we[4 * q + 3], s0);
            s1 = fmaf(y.x, we[4 * q + 0], s1);
            s1 = fmaf(y.y, we[4 * q + 1], s1);
            s1 = fmaf(y.z, we[4 * q + 2], s1);
            s1 = fmaf(y.w, we[4 * q + 3], s1);
            s2 = fmaf(z.x, we[4 * q + 0], s2);
            s2 = fmaf(z.y, we[4 * q + 1], s2);
            s2 = fmaf(z.z, we[4 * q + 2], s2);
            s2 = fmaf(z.w, we[4 * q + 3], s2);
            s3 = fmaf(v.x, we[4 * q + 0], s3);
            s3 = fmaf(v.y, we[4 * q + 1], s3);
            s3 = fmaf(v.z, we[4 * q + 2], s3);
            s3 = fmaf(v.w, we[4 * q + 3], s3);
        }
        msg = fmaf(a0, fmaxf(s0 + u0, 0.f), msg);
        msg = fmaf(a1, fmaxf(s1 + u1, 0.f), msg);
        msg = fmaf(a2, fmaxf(s2 + u2, 0.f), msg);
        msg = fmaf(a3, fmaxf(s3 + u3, 0.f), msg);
    }
    for (; idx < cnt; idx++) {
        int j0 = sj[idx];
        float a0 = sa[idx];
        float u0 = g_u[j0 * Ff + lane];
        const float4* p0 = tile + j0 * 4;
        float s0 = 0.f;
#pragma unroll
        for (int q = 0; q < 4; q++) {
            float4 x = p0[q];
            s0 = fmaf(x.x, we[4 * q + 0], s0);
            s0 = fmaf(x.y, we[4 * q + 1], s0);
            s0 = fmaf(x.z, we[4 * q + 2], s0);
            s0 = fmaf(x.w, we[4 * q + 3], s0);
        }
        msg = fmaf(a0, fmaxf(s0 + u0, 0.f), msg);
    }

    smsg[w * 32 + lane] = msg;
    __syncthreads();

    // ---- Phase 4: epilogue (warp 0) ----
    if (w == 0) {
        float m = 0.f;
#pragma unroll
        for (int k = 0; k < 16; k++) m += smsg[k * 32 + lane];
        float p = g_pre[i * Ff + lane] + m;  // (1+eps)*node_term + msg
        float acc = b_net[lane];
#pragma unroll
        for (int f = 0; f < Ff; f++)
            acc = fmaf(__shfl_sync(0xffffffffu, p, f), W_net[f * Kk + lane],
                       acc);
        out_y[(size_t)i * Kk + lane] = fmaxf(acc, 0.f);
    }
}

extern "C" void kernel_launch(void* const* d_in, const int* in_sizes, int n_in,
                              void* d_out, int out_size) {
    const float* adj = (const float*)d_in[0];
    const float* nodes = (const float*)d_in[1];
    const float* edges = (const float*)d_in[2];
    const float* W_ne = (const float*)d_in[3];
    const float* b_ne = (const float*)d_in[4];
    const float* W_n = (const float*)d_in[5];
    const float* b_n = (const float*)d_in[6];
    const float* W_net = (const float*)d_in[7];
    const float* b_net = (const float*)d_in[8];
    const float* eps = (const float*)d_in[9];

    float* out = (float*)d_out;
    float* out_adj = out;                                       // [N,N]
    float* out_y = out + (size_t)Nn * Nn;                       // [N,K]
    float* out_edges = out + (size_t)Nn * Nn + (size_t)Nn * Kk; // [N,N,E]

    // Idempotent, unconditional (no static guards allowed in kernel_launch).
    cudaFuncSetAttribute(fused_kernel,
                         cudaFuncAttributeMaxDynamicSharedMemorySize, SM_TOTAL);

    prep_kernel<<<(Nn * Ff) / 256, 256>>>(nodes, W_ne, b_ne, W_n, b_n, eps);
    fused_kernel<<<Nn, NT, SM_TOTAL>>>(adj, edges, W_ne, W_net, b_net, out_adj,
                                       out_y, out_edges);
}

// round 10
// speedup vs baseline: 1.4567x; 1.0985x over previous
#include <cuda_runtime.h>
#include <stdint.h>

#define Nn 2048
#define Ff 32
#define Ee 16
#define Kk 32

#define NT 256            // threads per block (8 warps)
#define NV (Nn * Ee / 4)  // 8192 float4 per edges row
#define CAP 320           // compacted tile capacity (slots)

// Scratch (device globals — no allocation allowed)
__device__ float g_u[Nn * Ff];    // node_part + b_ne
__device__ float g_pre[Nn * Ff];  // (1+eps) * relu(nodes@W_n + b_n)

// Kernel A: per-node precompute. 65536 threads, one per (j,f).
__global__ void prep_kernel(const float* __restrict__ nodes,
                            const float* __restrict__ W_ne,
                            const float* __restrict__ b_ne,
                            const float* __restrict__ W_n,
                            const float* __restrict__ b_n,
                            const float* __restrict__ eps) {
    int t = blockIdx.x * blockDim.x + threadIdx.x;  // 0..N*F-1
    int j = t >> 5;
    int f = t & 31;
    const float* nrow = nodes + j * Ff;
    float s1 = 0.f, s2 = 0.f;
#pragma unroll
    for (int c = 0; c < Ff; c++) {
        float nv = nrow[c];
        s1 = fmaf(nv, W_ne[c * Ff + f], s1);
        s2 = fmaf(nv, W_n[c * Ff + f], s2);
    }
    g_u[t] = s1 + b_ne[f];
    g_pre[t] = (1.0f + eps[0]) * fmaxf(s2 + b_n[f], 0.f);
}

// One block per row i, 256 threads (8 warps), ~38 KB smem -> 4 CTAs/SM.
//  1. adj scan + adj->out copy + per-warp ballot compaction (j, a) lists.
//  2. prefix over warp counts -> global slot per nnz; build j->slot map.
//  3. streaming copy of edges row; vectors whose j is nonzero are also
//     staged into a compacted 20 KB smem tile (~5% of vectors).
//  4. sparse msg from the compacted tile (LDS broadcast), g_u from
//     L2-resident table; 8 warps x ~13 nnz, 4-way MLP unroll.
//     slots >= CAP (pathological rows) fall back to global reads.
//  5. block reduce + 32x32 FC + relu.
__global__ __launch_bounds__(NT, 4) void fused_kernel(
    const float* __restrict__ adj,
    const float* __restrict__ edges,
    const float* __restrict__ W_ne,
    const float* __restrict__ W_net,
    const float* __restrict__ b_net,
    float* __restrict__ out_adj,
    float* __restrict__ out_y,
    float* __restrict__ out_edges) {
    __shared__ float4 ctile[CAP * 4];     // 20480 B compacted edge vectors
    __shared__ uint16_t s_slot[Nn];       // 4096 B  j -> slot (0xFFFF = none)
    __shared__ uint16_t sjb[8 * 256];     // 4096 B  per-warp nonzero j lists
    __shared__ float sab[8 * 256];        // 8192 B  per-warp adj values
    __shared__ int scnt[8];               // per-warp nnz counts
    __shared__ float smsg[8 * 32];        // partial messages

    int i = blockIdx.x;
    int t = threadIdx.x;
    int lane = t & 31;
    int w = t >> 5;  // 0..7

    const float* adjrow = adj + (size_t)i * Nn;
    float* oadj = out_adj + (size_t)i * Nn;
    const float4* erow4 =
        reinterpret_cast<const float4*>(edges + (size_t)i * Nn * Ee);
    float4* oe4 = reinterpret_cast<float4*>(out_edges + (size_t)i * Nn * Ee);

    // ---- Phase 0: init j->slot map ----
#pragma unroll
    for (int r = 0; r < Nn / NT; r++) s_slot[t + r * NT] = 0xFFFFu;

    // ---- Phase 1: adj scan + copy + compaction ----
    // Warp w owns j in {w*32 + c*256 + lane : c in [0,8)} — same partition
    // and order as R3/R9 -> identical summation order.
    uint16_t* sj = sjb + w * 256;
    float* sa = sab + w * 256;
    int cnt = 0;
#pragma unroll
    for (int c = 0; c < 8; c++) {
        int jb = w * 32 + c * NT;
        float a = adjrow[jb + lane];
        oadj[jb + lane] = a;  // fused adj pass-through copy
        unsigned mask = __ballot_sync(0xffffffffu, a != 0.f);
        int pos = cnt + __popc(mask & ((1u << lane) - 1u));
        if (a != 0.f) {
            sj[pos] = (uint16_t)(jb + lane);
            sa[pos] = a;
        }
        cnt += __popc(mask);
    }
    if (lane == 0) scnt[w] = cnt;
    __syncthreads();

    // ---- Phase 2a: prefix -> warp slot base; publish j->slot ----
    int wbase = 0;
#pragma unroll
    for (int k = 0; k < 8; k++) wbase += (k < w) ? scnt[k] : 0;
    for (int idx = lane; idx < cnt; idx += 32) {
        int slot = wbase + idx;
        if (slot < CAP) s_slot[sj[idx]] = (uint16_t)slot;
    }
    __syncthreads();

    // ---- Phase 2b: streaming copy + conditional compacted staging ----
#pragma unroll 8
    for (int r = 0; r < NV / NT; r++) {
        int k = t + r * NT;
        float4 v = erow4[k];
        oe4[k] = v;
        int slot = s_slot[k >> 2];
        if (slot != 0xFFFF) ctile[slot * 4 + (k & 3)] = v;
    }
    __syncthreads();

    // ---- Phase 3: sparse message from compacted tile, 4-way unrolled ----
    float we[Ee];
#pragma unroll
    for (int e = 0; e < Ee; e++) we[e] = W_ne[(Ff + e) * Ff + lane];

    float msg = 0.f;
    int idx = 0;
    if (wbase + cnt <= CAP) {
        // Fast path: all this warp's vectors are staged.
        for (; idx + 4 <= cnt; idx += 4) {
            int j0 = sj[idx], j1 = sj[idx + 1], j2 = sj[idx + 2],
                j3 = sj[idx + 3];
            float a0 = sa[idx], a1 = sa[idx + 1], a2 = sa[idx + 2],
                  a3 = sa[idx + 3];
            float u0 = g_u[j0 * Ff + lane];
            float u1 = g_u[j1 * Ff + lane];
            float u2 = g_u[j2 * Ff + lane];
            float u3 = g_u[j3 * Ff + lane];
            const float4* p0 = ctile + (wbase + idx) * 4;
            const float4* p1 = p0 + 4;
            const float4* p2 = p0 + 8;
            const float4* p3 = p0 + 12;
            float s0 = 0.f, s1 = 0.f, s2 = 0.f, s3 = 0.f;
#pragma unroll
            for (int q = 0; q < 4; q++) {
                float4 x = p0[q], y = p1[q], z = p2[q], v = p3[q];
                s0 = fmaf(x.x, we[4 * q + 0], s0);
                s0 = fmaf(x.y, we[4 * q + 1], s0);
                s0 = fmaf(x.z, we[4 * q + 2], s0);
                s0 = fmaf(x.w, we[4 * q + 3], s0);
                s1 = fmaf(y.x, we[4 * q + 0], s1);
                s1 = fmaf(y.y, we[4 * q + 1], s1);
                s1 = fmaf(y.z, we[4 * q + 2], s1);
                s1 = fmaf(y.w, we[4 * q + 3], s1);
                s2 = fmaf(z.x, we[4 * q + 0], s2);
                s2 = fmaf(z.y, we[4 * q + 1], s2);
                s2 = fmaf(z.z, we[4 * q + 2], s2);
                s2 = fmaf(z.w, we[4 * q + 3], s2);
                s3 = fmaf(v.x, we[4 * q + 0], s3);
                s3 = fmaf(v.y, we[4 * q + 1], s3);
                s3 = fmaf(v.z, we[4 * q + 2], s3);
                s3 = fmaf(v.w, we[4 * q + 3], s3);
            }
            msg = fmaf(a0, fmaxf(s0 + u0, 0.f), msg);
            msg = fmaf(a1, fmaxf(s1 + u1, 0.f), msg);
            msg = fmaf(a2, fmaxf(s2 + u2, 0.f), msg);
            msg = fmaf(a3, fmaxf(s3 + u3, 0.f), msg);
        }
    }
    // Tail + overflow fallback (slot >= CAP reads from global).
    for (; idx < cnt; idx++) {
        int j0 = sj[idx];
        float a0 = sa[idx];
        float u0 = g_u[j0 * Ff + lane];
        int slot = wbase + idx;
        float4 x0, x1, x2, x3;
        if (slot < CAP) {
            const float4* p0 = ctile + slot * 4;
            x0 = p0[0]; x1 = p0[1]; x2 = p0[2]; x3 = p0[3];
        } else {
            const float4* p0 = erow4 + (size_t)j0 * 4;
            x0 = p0[0]; x1 = p0[1]; x2 = p0[2]; x3 = p0[3];
        }
        float s0 = 0.f;
        s0 = fmaf(x0.x, we[0], s0);
        s0 = fmaf(x0.y, we[1], s0);
        s0 = fmaf(x0.z, we[2], s0);
        s0 = fmaf(x0.w, we[3], s0);
        s0 = fmaf(x1.x, we[4], s0);
        s0 = fmaf(x1.y, we[5], s0);
        s0 = fmaf(x1.z, we[6], s0);
        s0 = fmaf(x1.w, we[7], s0);
        s0 = fmaf(x2.x, we[8], s0);
        s0 = fmaf(x2.y, we[9], s0);
        s0 = fmaf(x2.z, we[10], s0);
        s0 = fmaf(x2.w, we[11], s0);
        s0 = fmaf(x3.x, we[12], s0);
        s0 = fmaf(x3.y, we[13], s0);
        s0 = fmaf(x3.z, we[14], s0);
        s0 = fmaf(x3.w, we[15], s0);
        msg = fmaf(a0, fmaxf(s0 + u0, 0.f), msg);
    }

    smsg[w * 32 + lane] = msg;
    __syncthreads();

    // ---- Phase 4: epilogue (warp 0) ----
    if (w == 0) {
        float m = 0.f;
#pragma unroll
        for (int k = 0; k < 8; k++) m += smsg[k * 32 + lane];
        float p = g_pre[i * Ff + lane] + m;  // (1+eps)*node_term + msg
        float acc = b_net[lane];
#pragma unroll
        for (int f = 0; f < Ff; f++)
            acc = fmaf(__shfl_sync(0xffffffffu, p, f), W_net[f * Kk + lane],
                       acc);
        out_y[(size_t)i * Kk + lane] = fmaxf(acc, 0.f);
    }
}

extern "C" void kernel_launch(void* const* d_in, const int* in_sizes, int n_in,
                              void* d_out, int out_size) {
    const float* adj = (const float*)d_in[0];
    const float* nodes = (const float*)d_in[1];
    const float* edges = (const float*)d_in[2];
    const float* W_ne = (const float*)d_in[3];
    const float* b_ne = (const float*)d_in[4];
    const float* W_n = (const float*)d_in[5];
    const float* b_n = (const float*)d_in[6];
    const float* W_net = (const float*)d_in[7];
    const float* b_net = (const float*)d_in[8];
    const float* eps = (const float*)d_in[9];

    float* out = (float*)d_out;
    float* out_adj = out;                                       // [N,N]
    float* out_y = out + (size_t)Nn * Nn;                       // [N,K]
    float* out_edges = out + (size_t)Nn * Nn + (size_t)Nn * Kk; // [N,N,E]

    prep_kernel<<<(Nn * Ff) / 256, 256>>>(nodes, W_ne, b_ne, W_n, b_n, eps);
    fused_kernel<<<Nn, NT>>>(adj, edges, W_ne, W_net, b_net, out_adj, out_y,
                             out_edges);
}